// round 8
// baseline (speedup 1.0000x reference)
#include <cuda_runtime.h>

#define C_IN  32
#define C_OUT 64
#define KNUM  8
#define TILE  1024
#define CHUNK 8
#define EPS   1e-5f

__device__ float g_sum[C_OUT];
__device__ float g_sumsq[C_OUT];
__device__ float g_a[C_OUT];
__device__ float g_b[C_OUT];

__device__ __forceinline__ unsigned long long pack2(float lo, float hi) {
    unsigned long long r;
    asm("mov.b64 %0, {%1, %2};" : "=l"(r) : "f"(lo), "f"(hi));
    return r;
}
__device__ __forceinline__ void unpack2(unsigned long long v, float& lo, float& hi) {
    asm("mov.b64 {%0, %1}, %2;" : "=f"(lo), "=f"(hi) : "l"(v));
}
#define FMA_F32X2(acc, a, b) \
    asm("fma.rn.f32x2 %0, %1, %2, %0;" : "+l"(acc) : "l"(a), "l"(b))

// ---------------------------------------------------------------------------
// Pass A: sparse conv + scatter. 8 warps/block; warp j owns kernel offset j,
// W[j] in registers as k-pair f32x2 operands (FFMA2); RED.64 scatter.
// x-rows staged GMEM->SMEM via cp.async, double-buffered CHUNK=8 voxels
// (one wait_group+syncwarp per 8 voxels, 8 rows in flight per warp).
// Binning uses warp-aggregated smem atomics (__match_any_sync): <=9 ATOMS
// per warp-round instead of 32.
// ---------------------------------------------------------------------------
__global__ void __launch_bounds__(256, 2)
conv_scatter(const float* __restrict__ x,
             const float* __restrict__ W,
             const int*   __restrict__ kidx,
             const int*   __restrict__ oidx,
             float*       __restrict__ out,
             int n)
{
    __shared__ int    bins[KNUM][TILE];
    __shared__ int    cnts[KNUM + 1];                   // [8] = invalid-lane bin
    __shared__ float4 xstage[KNUM][2][CHUNK][C_IN / 4]; // [warp][buf][slot][row]

    const int tid  = threadIdx.x;
    const int lane = tid & 31;
    const int wid  = tid >> 5;          // warp id == kernel offset j

    if (blockIdx.x == 0 && tid < C_OUT) { g_sum[tid] = 0.f; g_sumsq[tid] = 0.f; }

    // W[wid] packed for this lane's channel pair (2l, 2l+1), k-paired.
    unsigned long long wp0[C_IN / 2], wp1[C_IN / 2];
    {
        const float* Wj = W + wid * (C_IN * C_OUT);
        #pragma unroll
        for (int p = 0; p < C_IN / 2; ++p) {
            float2 ta = ((const float2*)(Wj + (2 * p)     * C_OUT))[lane];
            float2 tb = ((const float2*)(Wj + (2 * p + 1) * C_OUT))[lane];
            wp0[p] = pack2(ta.x, tb.x);
            wp1[p] = pack2(ta.y, tb.y);
        }
    }

    const int tileBase = blockIdx.x * TILE;

    if (tid <= KNUM) cnts[tid] = 0;
    __syncthreads();

    // Warp-aggregated binning.
    #pragma unroll
    for (int u = 0; u < TILE / 256; ++u) {
        int  i     = tileBase + u * 256 + tid;
        bool valid = (i < n);
        int  k     = valid ? kidx[i] : KNUM;
        unsigned mask   = __match_any_sync(0xffffffffu, k);
        int      leader = __ffs(mask) - 1;
        int      rank   = __popc(mask & ((1u << lane) - 1u));
        int      base   = 0;
        if (lane == leader) base = atomicAdd(&cnts[k], __popc(mask));
        base = __shfl_sync(0xffffffffu, base, leader);
        if (valid) bins[k][base + rank] = i;
    }
    __syncthreads();

    const int cnt = cnts[wid];
    if (cnt == 0) return;

    const unsigned xs_base =
        (unsigned)__cvta_generic_to_shared(&xstage[wid][0][0][0]);
    // buf stride = CHUNK*128B = 1024B; slot stride = 128B.

    // Prologue: stage chunk 0 into buffer 0; fetch its out-indices.
    int oq[CHUNK];
    #pragma unroll
    for (int d = 0; d < CHUNK; ++d) {
        if (d < cnt) {
            int i = bins[wid][d];
            const float* src = x + (size_t)i * C_IN + lane;
            unsigned dst = xs_base + d * 128 + lane * 4;
            asm volatile("cp.async.ca.shared.global [%0], [%1], 4;"
                         :: "r"(dst), "l"(src));
            oq[d] = oidx[i];
        } else oq[d] = 0;
    }
    asm volatile("cp.async.commit_group;");

    for (int base = 0; base < cnt; base += CHUNK) {
        const int buf = (base / CHUNK) & 1;

        // Stage NEXT chunk into the other buffer + fetch its out-indices.
        int on[CHUNK];
        #pragma unroll
        for (int d = 0; d < CHUNK; ++d) {
            int pf = base + CHUNK + d;
            if (pf < cnt) {
                int i = bins[wid][pf];
                const float* src = x + (size_t)i * C_IN + lane;
                unsigned dst = xs_base + (buf ^ 1) * (CHUNK * 128) + d * 128 + lane * 4;
                asm volatile("cp.async.ca.shared.global [%0], [%1], 4;"
                             :: "r"(dst), "l"(src));
                on[d] = oidx[i];
            } else on[d] = 0;
        }
        asm volatile("cp.async.commit_group;");

        // Current chunk complete (<=1 pending group), visible warp-wide.
        asm volatile("cp.async.wait_group 1;");
        __syncwarp();

        #pragma unroll
        for (int d = 0; d < CHUNK; ++d) {
            if (base + d < cnt) {
                const float4* xb = &xstage[wid][buf][d][0];
                unsigned long long acc0 = 0ull, acc1 = 0ull;
                #pragma unroll
                for (int t = 0; t < C_IN / 4; ++t) {
                    float4 v = xb[t];                         // broadcast LDS.128
                    unsigned long long v01 = pack2(v.x, v.y);
                    unsigned long long v23 = pack2(v.z, v.w);
                    FMA_F32X2(acc0, v01, wp0[2 * t]);
                    FMA_F32X2(acc1, v01, wp1[2 * t]);
                    FMA_F32X2(acc0, v23, wp0[2 * t + 1]);
                    FMA_F32X2(acc1, v23, wp1[2 * t + 1]);
                }
                float a0l, a0h, a1l, a1h;
                unpack2(acc0, a0l, a0h);
                unpack2(acc1, a1l, a1h);
                float a0 = a0l + a0h;       // channel 2*lane
                float a1 = a1l + a1h;       // channel 2*lane + 1

                float2* dst = (float2*)(out + (size_t)oq[d] * C_OUT) + lane;
                atomicAdd(dst, make_float2(a0, a1));   // RED.64
            }
        }

        #pragma unroll
        for (int d = 0; d < CHUNK; ++d) oq[d] = on[d];
    }
}

// ---------------------------------------------------------------------------
// Pass B: per-channel sum / sum-of-squares, float4 + unroll-4 for MLP.
// ---------------------------------------------------------------------------
__global__ void stats_pass(const float4* __restrict__ out4, int n4)
{
    float4 s  = make_float4(0.f, 0.f, 0.f, 0.f);
    float4 s2 = make_float4(0.f, 0.f, 0.f, 0.f);
    const int start  = blockIdx.x * blockDim.x + threadIdx.x;
    const int stride = blockDim.x * gridDim.x;   // multiple of 16
    for (int i = start; i < n4; i += 4 * stride) {
        #pragma unroll
        for (int u = 0; u < 4; ++u) {
            int j = i + u * stride;
            if (j < n4) {
                float4 v = out4[j];
                s.x += v.x; s.y += v.y; s.z += v.z; s.w += v.w;
                s2.x = fmaf(v.x, v.x, s2.x);
                s2.y = fmaf(v.y, v.y, s2.y);
                s2.z = fmaf(v.z, v.z, s2.z);
                s2.w = fmaf(v.w, v.w, s2.w);
            }
        }
    }

    __shared__ float sh1[C_OUT], sh2[C_OUT];
    if (threadIdx.x < C_OUT) { sh1[threadIdx.x] = 0.f; sh2[threadIdx.x] = 0.f; }
    __syncthreads();
    const int cg = (start & 15) * 4;             // fixed channel group base
    atomicAdd(&sh1[cg + 0], s.x);  atomicAdd(&sh1[cg + 1], s.y);
    atomicAdd(&sh1[cg + 2], s.z);  atomicAdd(&sh1[cg + 3], s.w);
    atomicAdd(&sh2[cg + 0], s2.x); atomicAdd(&sh2[cg + 1], s2.y);
    atomicAdd(&sh2[cg + 2], s2.z); atomicAdd(&sh2[cg + 3], s2.w);
    __syncthreads();
    if (threadIdx.x < C_OUT) {
        atomicAdd(&g_sum[threadIdx.x],   sh1[threadIdx.x]);
        atomicAdd(&g_sumsq[threadIdx.x], sh2[threadIdx.x]);
    }
}

// ---------------------------------------------------------------------------
// Pass C: finalize BN affine (conv bias cancels algebraically).
// ---------------------------------------------------------------------------
__global__ void finalize_stats(const float* __restrict__ gamma,
                               const float* __restrict__ beta,
                               float inv_n)
{
    const int c = threadIdx.x;
    float mean = g_sum[c] * inv_n;
    float var  = g_sumsq[c] * inv_n - mean * mean;
    float a    = gamma[c] * rsqrtf(var + EPS);
    g_a[c] = a;
    g_b[c] = fmaf(-mean, a, beta[c]);
}

// ---------------------------------------------------------------------------
// Pass D: in-place normalize + ReLU, float4 + unroll-4.
// ---------------------------------------------------------------------------
__global__ void norm_relu(float4* __restrict__ out4, int n4)
{
    const int start  = blockIdx.x * blockDim.x + threadIdx.x;
    const int stride = blockDim.x * gridDim.x;   // multiple of 16
    const int cg = (start & 15) * 4;
    const float4 a = *(const float4*)&g_a[cg];
    const float4 b = *(const float4*)&g_b[cg];
    for (int i = start; i < n4; i += 4 * stride) {
        float4 v[4]; bool has[4];
        #pragma unroll
        for (int u = 0; u < 4; ++u) {
            int j = i + u * stride;
            has[u] = (j < n4);
            if (has[u]) v[u] = out4[j];
        }
        #pragma unroll
        for (int u = 0; u < 4; ++u) {
            if (has[u]) {
                int j = i + u * stride;
                float4 w = v[u];
                w.x = fmaxf(fmaf(w.x, a.x, b.x), 0.f);
                w.y = fmaxf(fmaf(w.y, a.y, b.y), 0.f);
                w.z = fmaxf(fmaf(w.z, a.z, b.z), 0.f);
                w.w = fmaxf(fmaf(w.w, a.w, b.w), 0.f);
                out4[j] = w;
            }
        }
    }
}

// ---------------------------------------------------------------------------
// Launch. Inputs: x, W, bias, gamma, beta, k_idx, out_idx, num_out.
// ---------------------------------------------------------------------------
extern "C" void kernel_launch(void* const* d_in, const int* in_sizes, int n_in,
                              void* d_out, int out_size)
{
    const float* x     = (const float*)d_in[0];
    const float* W     = (const float*)d_in[1];
    const float* gamma = (const float*)d_in[3];
    const float* beta  = (const float*)d_in[4];
    const int*   kidx  = (const int*)d_in[5];
    const int*   oidx  = (const int*)d_in[6];

    const int n       = in_sizes[0] / C_IN;
    const int total   = out_size;               // num_out * 64
    const int num_out = total / C_OUT;
    const int n4      = total / 4;

    cudaMemsetAsync(d_out, 0, (size_t)total * sizeof(float), 0);

    const int tiles = (n + TILE - 1) / TILE;
    conv_scatter<<<tiles, 256>>>(x, W, kidx, oidx, (float*)d_out, n);
    stats_pass<<<1184, 256>>>((const float4*)d_out, n4);
    finalize_stats<<<1, C_OUT>>>(gamma, beta, 1.0f / (float)num_out);
    norm_relu<<<1184, 256>>>((float4*)d_out, n4);
}

// round 10
// speedup vs baseline: 1.0359x; 1.0359x over previous
#include <cuda_runtime.h>
#include <cstdint>

#define C_IN  32
#define C_OUT 64
#define KNUM  8
#define TILE  1024
#define NBUF  4
#define EPS   1e-5f

__device__ float g_sum[C_OUT];
__device__ float g_sumsq[C_OUT];
__device__ float g_a[C_OUT];
__device__ float g_b[C_OUT];

// xs FIRST: extern-shared base is >=128B aligned, so xs stays 16B aligned
// for cp.async 16B copies. (R9 crash: xs at offset 34856 = 8 mod 16.)
struct ConvSmem {
    float xs[KNUM][NBUF][16][C_IN];  // 64 KB, XOR-swizzled rows
    int   bins[KNUM][TILE];          // 32 KB
    int   o16[KNUM][NBUF][16];       // 2 KB
    int   cnts[KNUM + 2];
};

__device__ __forceinline__ uint32_t f2tf32(float f) {
    uint32_t r;
    asm("cvt.rna.tf32.f32 %0, %1;" : "=r"(r) : "f"(f));
    return r;
}

// ---------------------------------------------------------------------------
// Pass A: sparse conv + scatter via tf32 mma.sync (m16n8k8).
// 512 threads = 16 warps; warp pair (2j, 2j+1) owns kernel offset j.
// Warp 2j+h computes output channels [32h, 32h+32). W[j] held as tf32 B
// fragments in registers. 16 voxels per chunk: x-rows cp.async-staged into
// swizzled smem (ring of 4, prefetch distance 2), A fragments by direct LDS,
// 16 MMAs, scatter via float2 RED with slot-validity predicates.
// ---------------------------------------------------------------------------
__global__ void __launch_bounds__(512, 1)
conv_scatter(const float* __restrict__ x,
             const float* __restrict__ W,
             const int*   __restrict__ kidx,
             const int*   __restrict__ oidx,
             float*       __restrict__ out,
             int n)
{
    extern __shared__ char smem_raw[];
    ConvSmem* sm = reinterpret_cast<ConvSmem*>(smem_raw);

    const int tid  = threadIdx.x;
    const int lane = tid & 31;
    const int wid  = tid >> 5;       // 0..15
    const int j    = wid >> 1;       // kernel offset bin
    const int h    = wid & 1;        // channel half; h==0 also stages x

    if (blockIdx.x == 0 && tid < C_OUT) { g_sum[tid] = 0.f; g_sumsq[tid] = 0.f; }

    const int rl = lane >> 2;        // 0..7 (fragment row group / B col)
    const int e  = lane & 3;         // fragment k/col lane index

    // B fragments: bf[kt][nt] covers W[j][kt*8..kt*8+7][h*32 + nt*8 .. +7].
    uint32_t bf[4][4][2];
    {
        const float* Wj = W + j * (C_IN * C_OUT);
        #pragma unroll
        for (int kt = 0; kt < 4; ++kt)
            #pragma unroll
            for (int nt = 0; nt < 4; ++nt) {
                int col = h * 32 + nt * 8 + rl;
                bf[kt][nt][0] = f2tf32(Wj[(kt * 8 + e)     * C_OUT + col]);
                bf[kt][nt][1] = f2tf32(Wj[(kt * 8 + e + 4) * C_OUT + col]);
            }
    }

    // ---- Binning (warp-aggregated) ----
    const int tileBase = blockIdx.x * TILE;
    if (tid < KNUM + 2) sm->cnts[tid] = 0;
    __syncthreads();

    #pragma unroll
    for (int u = 0; u < TILE / 512; ++u) {
        int  i     = tileBase + u * 512 + tid;
        bool valid = (i < n);
        int  k     = valid ? kidx[i] : KNUM;
        unsigned mask   = __match_any_sync(0xffffffffu, k);
        int      leader = __ffs(mask) - 1;
        int      rank   = __popc(mask & ((1u << lane) - 1u));
        int      base   = 0;
        if (lane == leader) base = atomicAdd(&sm->cnts[k], __popc(mask));
        base = __shfl_sync(0xffffffffu, base, leader);
        if (valid) sm->bins[k][base + rank] = i;
    }
    __syncthreads();

    const int cnt = sm->cnts[j];
    if (cnt == 0) return;

    const uint32_t xs_smem =
        (uint32_t)__cvta_generic_to_shared(&sm->xs[j][0][0][0]);

    // Stage 16 x-rows of chunk 'base' into ring buffer 'buf' (warp h==0 only).
    // Row s stored with float-col swizzle c ^ ((s&7)<<2) -> conflict-free
    // A-fragment LDS later. One 16B cp.async per (row, 8-lane group).
    auto stage = [&](int base, int buf) {
        #pragma unroll
        for (int u = 0; u < 4; ++u) {
            int s   = u * 4 + (lane >> 3);
            int idx = base + s;
            if (idx < cnt) {
                int i = sm->bins[j][idx];
                const float* src = x + (size_t)i * C_IN + ((lane & 7) << 2);
                uint32_t fc  = (uint32_t)((((lane & 7) << 2) ^ ((s & 7) << 2)));
                uint32_t dst = xs_smem +
                    (uint32_t)(buf * 16 * C_IN + s * C_IN + fc) * 4u;
                asm volatile("cp.async.ca.shared.global [%0], [%1], 16;"
                             :: "r"(dst), "l"(src));
            }
        }
        if (lane < 16) {
            int idx = base + lane;
            sm->o16[j][buf][lane] = (idx < cnt) ? oidx[sm->bins[j][idx]] : 0;
        }
        asm volatile("cp.async.commit_group;");
    };

    if (h == 0) { stage(0, 0); stage(16, 1); }

    int it = 0;
    for (int base = 0; base < cnt; base += 16, ++it) {
        const int buf = it & 3;
        if (h == 0) {
            stage(base + 32, (it + 2) & 3);
            asm volatile("cp.async.wait_group 2;");
        }
        // Pair-scoped barrier: stager's smem writes visible to both warps.
        asm volatile("bar.sync %0, 64;" :: "r"(j + 1));

        const int  oa = sm->o16[j][buf][rl];
        const int  ob = sm->o16[j][buf][rl + 8];
        const bool va = (base + rl)     < cnt;
        const bool vb = (base + rl + 8) < cnt;

        float c[4][4];
        #pragma unroll
        for (int nt = 0; nt < 4; ++nt) {
            c[nt][0] = 0.f; c[nt][1] = 0.f; c[nt][2] = 0.f; c[nt][3] = 0.f;
        }

        const float* xb = &sm->xs[j][buf][0][0];
        #pragma unroll
        for (int kt = 0; kt < 4; ++kt) {
            int c0 = (kt * 8 + e)     ^ (rl << 2);
            int c4 = (kt * 8 + 4 + e) ^ (rl << 2);     // (rl+8)&7 == rl
            uint32_t a0 = f2tf32(xb[rl * C_IN + c0]);
            uint32_t a1 = f2tf32(xb[(rl + 8) * C_IN + c0]);
            uint32_t a2 = f2tf32(xb[rl * C_IN + c4]);
            uint32_t a3 = f2tf32(xb[(rl + 8) * C_IN + c4]);
            #pragma unroll
            for (int nt = 0; nt < 4; ++nt) {
                asm volatile(
                    "mma.sync.aligned.m16n8k8.row.col.f32.tf32.tf32.f32 "
                    "{%0,%1,%2,%3}, {%4,%5,%6,%7}, {%8,%9}, {%0,%1,%2,%3};"
                    : "+f"(c[nt][0]), "+f"(c[nt][1]),
                      "+f"(c[nt][2]), "+f"(c[nt][3])
                    : "r"(a0), "r"(a1), "r"(a2), "r"(a3),
                      "r"(bf[kt][nt][0]), "r"(bf[kt][nt][1]));
            }
        }

        // Scatter: c0,c1 -> row rl (oa); c2,c3 -> row rl+8 (ob).
        #pragma unroll
        for (int nt = 0; nt < 4; ++nt) {
            int coloff = h * 32 + nt * 8 + (e << 1);
            if (va) atomicAdd((float2*)(out + (size_t)oa * C_OUT + coloff),
                              make_float2(c[nt][0], c[nt][1]));
            if (vb) atomicAdd((float2*)(out + (size_t)ob * C_OUT + coloff),
                              make_float2(c[nt][2], c[nt][3]));
        }
    }
    if (h == 0) asm volatile("cp.async.wait_group 0;");
}

// ---------------------------------------------------------------------------
// Pass B: per-channel sum / sum-of-squares, float4 + unroll-4.
// ---------------------------------------------------------------------------
__global__ void stats_pass(const float4* __restrict__ out4, int n4)
{
    float4 s  = make_float4(0.f, 0.f, 0.f, 0.f);
    float4 s2 = make_float4(0.f, 0.f, 0.f, 0.f);
    const int start  = blockIdx.x * blockDim.x + threadIdx.x;
    const int stride = blockDim.x * gridDim.x;   // multiple of 16
    for (int i = start; i < n4; i += 4 * stride) {
        #pragma unroll
        for (int u = 0; u < 4; ++u) {
            int jx = i + u * stride;
            if (jx < n4) {
                float4 v = out4[jx];
                s.x += v.x; s.y += v.y; s.z += v.z; s.w += v.w;
                s2.x = fmaf(v.x, v.x, s2.x);
                s2.y = fmaf(v.y, v.y, s2.y);
                s2.z = fmaf(v.z, v.z, s2.z);
                s2.w = fmaf(v.w, v.w, s2.w);
            }
        }
    }

    __shared__ float sh1[C_OUT], sh2[C_OUT];
    if (threadIdx.x < C_OUT) { sh1[threadIdx.x] = 0.f; sh2[threadIdx.x] = 0.f; }
    __syncthreads();
    const int cg = (start & 15) * 4;
    atomicAdd(&sh1[cg + 0], s.x);  atomicAdd(&sh1[cg + 1], s.y);
    atomicAdd(&sh1[cg + 2], s.z);  atomicAdd(&sh1[cg + 3], s.w);
    atomicAdd(&sh2[cg + 0], s2.x); atomicAdd(&sh2[cg + 1], s2.y);
    atomicAdd(&sh2[cg + 2], s2.z); atomicAdd(&sh2[cg + 3], s2.w);
    __syncthreads();
    if (threadIdx.x < C_OUT) {
        atomicAdd(&g_sum[threadIdx.x],   sh1[threadIdx.x]);
        atomicAdd(&g_sumsq[threadIdx.x], sh2[threadIdx.x]);
    }
}

// ---------------------------------------------------------------------------
// Pass C: finalize BN affine (conv bias cancels algebraically).
// ---------------------------------------------------------------------------
__global__ void finalize_stats(const float* __restrict__ gamma,
                               const float* __restrict__ beta,
                               float inv_n)
{
    const int c = threadIdx.x;
    float mean = g_sum[c] * inv_n;
    float var  = g_sumsq[c] * inv_n - mean * mean;
    float a    = gamma[c] * rsqrtf(var + EPS);
    g_a[c] = a;
    g_b[c] = fmaf(-mean, a, beta[c]);
}

// ---------------------------------------------------------------------------
// Pass D: in-place normalize + ReLU, float4 + unroll-2 (regs=28 variant).
// ---------------------------------------------------------------------------
__global__ void norm_relu(float4* __restrict__ out4, int n4)
{
    const int start  = blockIdx.x * blockDim.x + threadIdx.x;
    const int stride = blockDim.x * gridDim.x;   // multiple of 16
    const int cg = (start & 15) * 4;
    const float4 a = *(const float4*)&g_a[cg];
    const float4 b = *(const float4*)&g_b[cg];
    for (int i = start; i < n4; i += 2 * stride) {
        float4 v0 = out4[i];
        int jx = i + stride;
        bool has1 = (jx < n4);
        float4 v1 = has1 ? out4[jx] : make_float4(0.f, 0.f, 0.f, 0.f);
        v0.x = fmaxf(fmaf(v0.x, a.x, b.x), 0.f);
        v0.y = fmaxf(fmaf(v0.y, a.y, b.y), 0.f);
        v0.z = fmaxf(fmaf(v0.z, a.z, b.z), 0.f);
        v0.w = fmaxf(fmaf(v0.w, a.w, b.w), 0.f);
        out4[i] = v0;
        if (has1) {
            v1.x = fmaxf(fmaf(v1.x, a.x, b.x), 0.f);
            v1.y = fmaxf(fmaf(v1.y, a.y, b.y), 0.f);
            v1.z = fmaxf(fmaf(v1.z, a.z, b.z), 0.f);
            v1.w = fmaxf(fmaf(v1.w, a.w, b.w), 0.f);
            out4[jx] = v1;
        }
    }
}

// ---------------------------------------------------------------------------
// Launch. Inputs: x, W, bias, gamma, beta, k_idx, out_idx, num_out.
// ---------------------------------------------------------------------------
extern "C" void kernel_launch(void* const* d_in, const int* in_sizes, int n_in,
                              void* d_out, int out_size)
{
    const float* x     = (const float*)d_in[0];
    const float* W     = (const float*)d_in[1];
    const float* gamma = (const float*)d_in[3];
    const float* beta  = (const float*)d_in[4];
    const int*   kidx  = (const int*)d_in[5];
    const int*   oidx  = (const int*)d_in[6];

    const int n       = in_sizes[0] / C_IN;
    const int total   = out_size;               // num_out * 64
    const int num_out = total / C_OUT;
    const int n4      = total / 4;

    const int smem_bytes = (int)sizeof(ConvSmem);   // ~100 KB
    cudaFuncSetAttribute(conv_scatter,
                         cudaFuncAttributeMaxDynamicSharedMemorySize,
                         smem_bytes);

    cudaMemsetAsync(d_out, 0, (size_t)total * sizeof(float), 0);

    const int tiles = (n + TILE - 1) / TILE;
    conv_scatter<<<tiles, 512, smem_bytes>>>(x, W, kidx, oidx, (float*)d_out, n);
    stats_pass<<<1184, 256>>>((const float4*)d_out, n4);
    finalize_stats<<<1, C_OUT>>>(gamma, beta, 1.0f / (float)num_out);
    norm_relu<<<1184, 256>>>((float4*)d_out, n4);
}